// round 12
// baseline (speedup 1.0000x reference)
#include <cuda_runtime.h>
#include <cuda_bf16.h>
#include <cstdint>
#include <math.h>

#define SS 128
#define QQ 256
#define CC 256
#define HH 8
#define CHD 32
#define MROWS (SS*QQ)

// ---------------------------------------------------------------------------
// Helpers
// ---------------------------------------------------------------------------
__device__ __forceinline__ uint32_t smem_u32(const void* p) {
    uint32_t a;
    asm("{ .reg .u64 t; cvta.to.shared.u64 t, %1; cvt.u32.u64 %0, t; }" : "=r"(a) : "l"(p));
    return a;
}
__device__ __forceinline__ void cp16(uint32_t dst, const void* src) {
    asm volatile("cp.async.cg.shared.global [%0], [%1], 16;" :: "r"(dst), "l"(src));
}
__device__ __forceinline__ void ldmx4(uint32_t* f, uint32_t addr) {
    asm volatile("ldmatrix.sync.aligned.m8n8.x4.shared.b16 {%0,%1,%2,%3}, [%4];"
                 : "=r"(f[0]), "=r"(f[1]), "=r"(f[2]), "=r"(f[3]) : "r"(addr));
}
__device__ __forceinline__ void mma16816(float* c, const uint32_t* a, uint32_t b0, uint32_t b1) {
    asm volatile("mma.sync.aligned.m16n8k16.row.col.f32.bf16.bf16.f32 "
                 "{%0,%1,%2,%3}, {%4,%5,%6,%7}, {%8,%9}, {%0,%1,%2,%3};"
                 : "+f"(c[0]), "+f"(c[1]), "+f"(c[2]), "+f"(c[3])
                 : "r"(a[0]), "r"(a[1]), "r"(a[2]), "r"(a[3]), "r"(b0), "r"(b1));
}
__device__ __forceinline__ uint32_t packbf(float hi, float lo) {
    uint32_t pk;
    asm("cvt.rn.satfinite.bf16x2.f32 %0, %1, %2;" : "=r"(pk) : "f"(hi), "f"(lo));
    return pk;
}

// ---------------------------------------------------------------------------
// Scratch (device globals: allocation-free rule)
// ---------------------------------------------------------------------------
__device__ __nv_bfloat16 g_xb[MROWS * 256];        // input in bf16
__device__ __nv_bfloat16 g_wb[1024 * 256];         // packed wq|wk|wv|wg (wq pre-scaled)
__device__ __nv_bfloat16 g_wob[256 * 256];         // wo in bf16
__device__ __nv_bfloat16 g_qb[SS * HH * QQ * CHD]; // [s,h,q,d] bf16
__device__ __nv_bfloat16 g_kb[SS * HH * QQ * CHD];
__device__ __nv_bfloat16 g_vb[SS * HH * QQ * CHD];
__device__ __nv_bfloat16 g_gateb[MROWS * 256];     // sigmoid gate (bf16), [row, e]
__device__ __nv_bfloat16 g_ob[MROWS * 256];        // gated attention output (bf16)
__device__ __nv_bfloat16 g_biasb[HH * QQ * QQ];    // bias in bf16

// ---------------------------------------------------------------------------
// Prologue: one kernel, grid-partitioned (conv_x | conv_bias | pack_w)
// ---------------------------------------------------------------------------
__global__ void prep(const float* __restrict__ x, const float* __restrict__ bias,
                     const float* __restrict__ wq, const float* __restrict__ wk,
                     const float* __restrict__ wv, const float* __restrict__ wg,
                     const float* __restrict__ wo) {
    int b = blockIdx.x;
    if (b < 8192) {                       // conv_x: 2,097,152 quads
        int i = b * 256 + threadIdx.x;
        float4 v = ((const float4*)x)[i];
        __nv_bfloat162* dst = (__nv_bfloat162*)g_xb;
        dst[2 * i]     = __floats2bfloat162_rn(v.x, v.y);
        dst[2 * i + 1] = __floats2bfloat162_rn(v.z, v.w);
    } else if (b < 8704) {                // conv_bias: 131,072 quads
        int i = (b - 8192) * 256 + threadIdx.x;
        float4 v = ((const float4*)bias)[i];
        __nv_bfloat162* dst = (__nv_bfloat162*)g_biasb;
        dst[2 * i]     = __floats2bfloat162_rn(v.x, v.y);
        dst[2 * i + 1] = __floats2bfloat162_rn(v.z, v.w);
    } else {                              // pack_w: 1280 rows
        int e = b - 8704;
        int c = threadIdx.x;
        if (e < 1024) {
            float val;
            if (e < 256)      val = wq[e * 256 + c] * 0.17677669529663687f;
            else if (e < 512) val = wk[(e - 256) * 256 + c];
            else if (e < 768) val = wv[(e - 512) * 256 + c];
            else              val = wg[(e - 768) * 256 + c];
            g_wb[e * 256 + c] = __float2bfloat16(val);
        } else {
            int r = e - 1024;
            g_wob[r * 256 + c] = __float2bfloat16(wo[r * 256 + c]);
        }
    }
}

// ---------------------------------------------------------------------------
// GEMM core: C[128,64] = A[128,256] x B[64,256]^T (NT, bf16, f32 acc)
// 8 warps as 4(M) x 2(N); per warp 32x32. 3-stage cp.async, 1 barrier/iter.
// ---------------------------------------------------------------------------
#define TILE_A 10240            // 128 rows * 80 bytes
#define TILE_BB 5120            // 64 rows * 80 bytes
#define STAGE_B (TILE_A + TILE_BB)
#define GEMM_SMEM (3 * STAGE_B) // 46080

__device__ __forceinline__ void gemm_core(const __nv_bfloat16* __restrict__ gA,
                                          const __nv_bfloat16* __restrict__ gB,
                                          char* smem,
                                          float acc[2][4][4]) {
    const int tid = threadIdx.x, lane = tid & 31, wid = tid >> 5;
    const int wm0 = (wid >> 1) * 32, wn0 = (wid & 1) * 32;
    const uint32_t sbase = smem_u32(smem);

    #pragma unroll
    for (int mt = 0; mt < 2; mt++)
        #pragma unroll
        for (int nt = 0; nt < 4; nt++)
            #pragma unroll
            for (int i = 0; i < 4; i++) acc[mt][nt][i] = 0.f;

    auto load_tile = [&](int buf, int k0) {
        uint32_t st = sbase + buf * STAGE_B;
        #pragma unroll
        for (int j = 0; j < 2; j++) {           // A: 512 chunks
            int idx = tid + j * 256;
            int r = idx >> 2, ch = idx & 3;
            cp16(st + r * 80 + ch * 16, gA + r * 256 + k0 + ch * 8);
        }
        {                                        // B: 256 chunks
            int r = tid >> 2, ch = tid & 3;
            cp16(st + TILE_A + r * 80 + ch * 16, gB + r * 256 + k0 + ch * 8);
        }
        asm volatile("cp.async.commit_group;" ::: "memory");
    };

    load_tile(0, 0);
    load_tile(1, 32);

    #pragma unroll
    for (int kit = 0; kit < 8; kit++) {
        if (kit < 7) {
            asm volatile("cp.async.wait_group 1;" ::: "memory");
        } else {
            asm volatile("cp.async.wait_group 0;" ::: "memory");
        }
        __syncthreads();   // all threads waited -> tile kit visible; compute kit-1 done
        if (kit < 6) {
            load_tile((kit + 2) % 3, (kit + 2) * 32);
        }
        const uint32_t ab = sbase + (kit % 3) * STAGE_B;
        const uint32_t bb = ab + TILE_A;
        #pragma unroll
        for (int kk = 0; kk < 2; kk++) {
            uint32_t af[2][4];
            #pragma unroll
            for (int mt = 0; mt < 2; mt++) {
                int row = wm0 + mt * 16 + (lane & 15);
                int col = kk * 16 + ((lane >> 4) << 3);
                ldmx4(af[mt], ab + row * 80 + col * 2);
            }
            #pragma unroll
            for (int nt2 = 0; nt2 < 2; nt2++) {
                uint32_t bf[4];
                int nrow = wn0 + nt2 * 16 + (lane & 7) + ((lane >> 4) << 3);
                int ncol = kk * 16 + (((lane >> 3) & 1) << 3);
                ldmx4(bf, bb + nrow * 80 + ncol * 2);
                #pragma unroll
                for (int mt = 0; mt < 2; mt++) {
                    mma16816(acc[mt][2 * nt2],     af[mt], bf[0], bf[1]);
                    mma16816(acc[mt][2 * nt2 + 1], af[mt], bf[2], bf[3]);
                }
            }
        }
    }
}

// ---------------------------------------------------------------------------
// GEMM1: Y[32768,1024] = Xb @ Wb^T. BN=64, grid (16, 256).
// ---------------------------------------------------------------------------
__global__ __launch_bounds__(256, 3) void gemm1_mma(const float* __restrict__ bg) {
    extern __shared__ char dynsm[];
    const int bn = blockIdx.x, bm = blockIdx.y;
    const int lane = threadIdx.x & 31, wid = threadIdx.x >> 5;
    const int wm0 = (wid >> 1) * 32, wn0 = (wid & 1) * 32;

    float acc[2][4][4];
    gemm_core(g_xb + (size_t)bm * 128 * 256, g_wb + (size_t)bn * 64 * 256, dynsm, acc);

    #pragma unroll
    for (int mt = 0; mt < 2; mt++) {
        #pragma unroll
        for (int nt = 0; nt < 4; nt++) {
            #pragma unroll
            for (int half = 0; half < 2; half++) {
                int m = bm * 128 + wm0 + mt * 16 + (lane >> 2) + half * 8;
                int e = bn * 64 + wn0 + nt * 8 + 2 * (lane & 3);
                float v0 = acc[mt][nt][2 * half];
                float v1 = acc[mt][nt][2 * half + 1];
                int s = m >> 8, q = m & 255;
                if (e < 768) {
                    int which = e >> 8;
                    int h = (e >> 5) & 7;
                    int d = e & 31;
                    __nv_bfloat16* dst = (which == 0 ? g_qb : (which == 1 ? g_kb : g_vb)) +
                                         ((size_t)(s * 8 + h) * 256 + q) * 32 + d;
                    *(uint32_t*)dst = packbf(v1, v0);
                } else {
                    int eg = e - 768;
                    float g0 = 1.0f / (1.0f + __expf(-(v0 + bg[eg])));
                    float g1 = 1.0f / (1.0f + __expf(-(v1 + bg[eg + 1])));
                    *(uint32_t*)(g_gateb + (size_t)m * 256 + eg) = packbf(g1, g0);
                }
            }
        }
    }
}

// ---------------------------------------------------------------------------
// GEMM2: out[q,s,c] = addt + g_ob @ wo^T + bo. BN=64, grid (4, 256).
// ---------------------------------------------------------------------------
__global__ __launch_bounds__(256, 3) void gemm2_mma(const float* __restrict__ bo,
                                                    const float* __restrict__ addt,
                                                    float* __restrict__ out) {
    extern __shared__ char dynsm[];
    const int bn = blockIdx.x, bm = blockIdx.y;
    const int lane = threadIdx.x & 31, wid = threadIdx.x >> 5;
    const int wm0 = (wid >> 1) * 32, wn0 = (wid & 1) * 32;

    float acc[2][4][4];
    gemm_core(g_ob + (size_t)bm * 128 * 256, g_wob + (size_t)bn * 64 * 256, dynsm, acc);

    #pragma unroll
    for (int mt = 0; mt < 2; mt++) {
        #pragma unroll
        for (int nt = 0; nt < 4; nt++) {
            #pragma unroll
            for (int half = 0; half < 2; half++) {
                int m = bm * 128 + wm0 + mt * 16 + (lane >> 2) + half * 8;
                int c = bn * 64 + wn0 + nt * 8 + 2 * (lane & 3);
                int s = m >> 8, q = m & 255;
                size_t oi = ((size_t)q * 128 + s) * 256 + c;
                float2 a2 = *(const float2*)(addt + oi);
                float2 b2 = *(const float2*)(bo + c);
                float2 r2;
                r2.x = a2.x + b2.x + acc[mt][nt][2 * half];
                r2.y = a2.y + b2.y + acc[mt][nt][2 * half + 1];
                *(float2*)(out + oi) = r2;
            }
        }
    }
}

// ---------------------------------------------------------------------------
// Tensor-core flash attention. One CTA per (s,h), 8 warps x 32 q-rows.
// Bias staged through smem via double-buffered cp.async (2 chunks ahead).
// ---------------------------------------------------------------------------
#define QS_OFF    0         // 256 rows x 80B
#define KS_OFF    20480     // 256 rows x 80B
#define VT_OFF    40960     // Vt: 32 rows x 528B
#define MADD_OFF  57856     // 256 floats
#define BIAS_OFF  58880     // 2 buffers x (256 rows x 80B)
#define BIAS_BUF  20480
#define ATTN_SMEM (BIAS_OFF + 2 * BIAS_BUF)   // 99840

__global__ __launch_bounds__(256) void attn_tc(const float* __restrict__ mask) {
    extern __shared__ char smp[];
    const uint32_t sb = smem_u32(smp);
    const int s = blockIdx.x >> 3;
    const int h = blockIdx.x & 7;
    const int t = threadIdx.x;
    const int lane = t & 31, w = t >> 5;

    const size_t hb = (size_t)(s * 8 + h) * 16384;   // byte offset of this (s,h) tile

    // bias chunk loader: 256 rows x 64B (32 bf16), 80B pitch; one row per thread
    auto load_bias = [&](int buf, int c) {
        const char* src = (const char*)g_biasb + ((size_t)h * 256 + t) * 512 + c * 64;
        uint32_t dst = sb + BIAS_OFF + buf * BIAS_BUF + t * 80;
        cp16(dst, src);
        cp16(dst + 16, src + 16);
        cp16(dst + 32, src + 32);
        cp16(dst + 48, src + 48);
        asm volatile("cp.async.commit_group;" ::: "memory");
    };

    // cp.async Q, K tiles into 80B-pitch smem (committed with bias chunk 0 = G0)
    #pragma unroll
    for (int j = 0; j < 4; j++) {
        int idx = t + j * 256;
        int r = idx >> 2, ch = idx & 3;
        cp16(sb + QS_OFF + r * 80 + ch * 16, (const char*)g_qb + hb + r * 64 + ch * 16);
        cp16(sb + KS_OFF + r * 80 + ch * 16, (const char*)g_kb + hb + r * 64 + ch * 16);
    }
    load_bias(0, 0);   // G0 = QK + bias0
    load_bias(1, 1);   // G1 = bias1

    // V transpose: thread t reads V row k=t (32 bf16), scatters to Vt[d][k=t]
    {
        union { uint4 v4[4]; uint16_t u16[32]; } tv;
        const uint4* vr = (const uint4*)((const char*)g_vb + hb + t * 64);
        tv.v4[0] = vr[0]; tv.v4[1] = vr[1]; tv.v4[2] = vr[2]; tv.v4[3] = vr[3];
        #pragma unroll
        for (int d = 0; d < 32; d++)
            *(uint16_t*)(smp + VT_OFF + d * 528 + 2 * t) = tv.u16[d];
    }
    // mask additive term
    *(float*)(smp + MADD_OFF + 4 * t) = (mask[s * 256 + t] - 1.0f) * 1e9f;

    asm volatile("cp.async.wait_group 1;" ::: "memory");   // G0 done (QK + bias0)
    __syncthreads();

    // Q fragments for this warp's 32 rows
    uint32_t af[2][2][4];   // [mt][kstep]
    #pragma unroll
    for (int mt = 0; mt < 2; mt++)
        #pragma unroll
        for (int ks = 0; ks < 2; ks++) {
            int row = 32 * w + mt * 16 + (lane & 15);
            int col = ks * 16 + ((lane >> 4) << 3);
            ldmx4(af[mt][ks], sb + QS_OFF + row * 80 + col * 2);
        }

    float o_acc[2][4][4];
    #pragma unroll
    for (int mt = 0; mt < 2; mt++)
        #pragma unroll
        for (int nt = 0; nt < 4; nt++)
            #pragma unroll
            for (int i = 0; i < 4; i++) o_acc[mt][nt][i] = 0.f;
    float lsum[2][2] = {};

    const int r_lo = (lane >> 2);         // row-in-tile for c0,c1
    const int jo   = 2 * (lane & 3);      // col pair offset

    for (int c = 0; c < 8; c++) {
        // ---- S = Q K^T for this 32-key chunk ----
        float s_acc[2][4][4];
        #pragma unroll
        for (int mt = 0; mt < 2; mt++)
            #pragma unroll
            for (int nt = 0; nt < 4; nt++)
                #pragma unroll
                for (int i = 0; i < 4; i++) s_acc[mt][nt][i] = 0.f;

        #pragma unroll
        for (int ks = 0; ks < 2; ks++) {
            #pragma unroll
            for (int nt2 = 0; nt2 < 2; nt2++) {
                uint32_t bf[4];
                int nrow = c * 32 + nt2 * 16 + (lane & 7) + ((lane >> 4) << 3);
                int ncol = ks * 16 + (((lane >> 3) & 1) << 3);
                ldmx4(bf, sb + KS_OFF + nrow * 80 + ncol * 2);
                #pragma unroll
                for (int mt = 0; mt < 2; mt++) {
                    mma16816(s_acc[mt][2 * nt2],     af[mt][ks], bf[0], bf[1]);
                    mma16816(s_acc[mt][2 * nt2 + 1], af[mt][ks], bf[2], bf[3]);
                }
            }
        }

        // ---- wait for this chunk's bias, make visible ----
        if (c < 7) {
            asm volatile("cp.async.wait_group 1;" ::: "memory");
        } else {
            asm volatile("cp.async.wait_group 0;" ::: "memory");
        }
        __syncthreads();

        // ---- bias(smem) + mask, exp, pack P fragments ----
        const uint32_t bbase = sb + BIAS_OFF + (c & 1) * BIAS_BUF;
        uint32_t pfrag[2][4][2];
        #pragma unroll
        for (int mt = 0; mt < 2; mt++) {
            int r0 = 32 * w + mt * 16 + r_lo;
            #pragma unroll
            for (int nt = 0; nt < 4; nt++) {
                int jl = nt * 8 + jo;                 // 0..31 within chunk
                int j = c * 32 + jl;
                float2 mj = *(const float2*)(smp + MADD_OFF + 4 * j);
                __nv_bfloat162 bb0 = *(const __nv_bfloat162*)(uintptr_t)0;  // placeholder avoided
                // read via smem pointers (conflict-free: bank=(q*20+l)%32)
                __nv_bfloat162 b0v, b1v;
                asm volatile("ld.shared.b32 %0, [%1];" : "=r"(*(uint32_t*)&b0v)
                             : "r"(bbase + r0 * 80 + jl * 2));
                asm volatile("ld.shared.b32 %0, [%1];" : "=r"(*(uint32_t*)&b1v)
                             : "r"(bbase + (r0 + 8) * 80 + jl * 2));
                float2 b0 = __bfloat1622float2(b0v);
                float2 b1 = __bfloat1622float2(b1v);
                (void)bb0;
                float w00 = __expf(fminf(s_acc[mt][nt][0] + b0.x + mj.x, 80.f));
                float w01 = __expf(fminf(s_acc[mt][nt][1] + b0.y + mj.y, 80.f));
                float w10 = __expf(fminf(s_acc[mt][nt][2] + b1.x + mj.x, 80.f));
                float w11 = __expf(fminf(s_acc[mt][nt][3] + b1.y + mj.y, 80.f));
                lsum[mt][0] += w00 + w01;
                lsum[mt][1] += w10 + w11;
                pfrag[mt][nt][0] = packbf(w01, w00);
                pfrag[mt][nt][1] = packbf(w11, w10);
            }
        }

        // ---- O += P V ----
        #pragma unroll
        for (int ks2 = 0; ks2 < 2; ks2++) {
            uint32_t bv[2][4];
            #pragma unroll
            for (int nv = 0; nv < 2; nv++) {
                int nrow = nv * 16 + (lane & 7) + ((lane >> 4) << 3);
                int ncol = c * 32 + ks2 * 16 + (((lane >> 3) & 1) << 3);
                ldmx4(bv[nv], sb + VT_OFF + nrow * 528 + ncol * 2);
            }
            #pragma unroll
            for (int mt = 0; mt < 2; mt++) {
                uint32_t aP[4] = { pfrag[mt][2 * ks2][0], pfrag[mt][2 * ks2][1],
                                   pfrag[mt][2 * ks2 + 1][0], pfrag[mt][2 * ks2 + 1][1] };
                #pragma unroll
                for (int nv = 0; nv < 2; nv++) {
                    mma16816(o_acc[mt][2 * nv],     aP, bv[nv][0], bv[nv][1]);
                    mma16816(o_acc[mt][2 * nv + 1], aP, bv[nv][2], bv[nv][3]);
                }
            }
        }

        // ---- prefetch bias chunk c+2 into buf c%2 (all warps done reading it) ----
        if (c < 6) {
            __syncthreads();
            load_bias(c & 1, c + 2);
        }
    }

    // ---- row-sum reduce + normalize + gate + store ----
    float inv[2][2];
    #pragma unroll
    for (int mt = 0; mt < 2; mt++)
        #pragma unroll
        for (int half = 0; half < 2; half++) {
            float lv = lsum[mt][half];
            lv += __shfl_xor_sync(0xffffffffu, lv, 1);
            lv += __shfl_xor_sync(0xffffffffu, lv, 2);
            inv[mt][half] = 1.0f / lv;
        }

    #pragma unroll
    for (int mt = 0; mt < 2; mt++) {
        int q0 = 32 * w + mt * 16 + r_lo;
        int row0 = s * 256 + q0;
        #pragma unroll
        for (int nv = 0; nv < 4; nv++) {
            int d = nv * 8 + jo;
            __nv_bfloat162 gav = *(const __nv_bfloat162*)(g_gateb + (size_t)row0 * 256 + h * 32 + d);
            __nv_bfloat162 gbv = *(const __nv_bfloat162*)(g_gateb + (size_t)(row0 + 8) * 256 + h * 32 + d);
            float2 ga = __bfloat1622float2(gav);
            float2 gb = __bfloat1622float2(gbv);
            float v00 = o_acc[mt][nv][0] * inv[mt][0] * ga.x;
            float v01 = o_acc[mt][nv][1] * inv[mt][0] * ga.y;
            float v10 = o_acc[mt][nv][2] * inv[mt][1] * gb.x;
            float v11 = o_acc[mt][nv][3] * inv[mt][1] * gb.y;
            *(uint32_t*)(g_ob + (size_t)row0 * 256 + h * 32 + d) = packbf(v01, v00);
            *(uint32_t*)(g_ob + (size_t)(row0 + 8) * 256 + h * 32 + d) = packbf(v11, v10);
        }
    }
}

// ---------------------------------------------------------------------------
extern "C" void kernel_launch(void* const* d_in, const int* in_sizes, int n_in,
                              void* d_out, int out_size) {
    const float* x    = (const float*)d_in[0];
    const float* mask = (const float*)d_in[1];
    const float* bias = (const float*)d_in[2];
    const float* addt = (const float*)d_in[3];
    const float* wq   = (const float*)d_in[4];
    const float* wk   = (const float*)d_in[5];
    const float* wv   = (const float*)d_in[6];
    const float* wg   = (const float*)d_in[7];
    const float* bg   = (const float*)d_in[8];
    const float* wo   = (const float*)d_in[9];
    const float* bo   = (const float*)d_in[10];
    float* out = (float*)d_out;

    cudaFuncSetAttribute(attn_tc, cudaFuncAttributeMaxDynamicSharedMemorySize, ATTN_SMEM);
    cudaFuncSetAttribute(gemm1_mma, cudaFuncAttributeMaxDynamicSharedMemorySize, GEMM_SMEM);
    cudaFuncSetAttribute(gemm2_mma, cudaFuncAttributeMaxDynamicSharedMemorySize, GEMM_SMEM);

    prep<<<9984, 256>>>(x, bias, wq, wk, wv, wg, wo);

    gemm1_mma<<<dim3(16, 256), 256, GEMM_SMEM>>>(bg);
    attn_tc<<<1024, 256, ATTN_SMEM>>>(mask);
    gemm2_mma<<<dim3(4, 256), 256, GEMM_SMEM>>>(bo, addt, out);
}

// round 13
// speedup vs baseline: 1.0520x; 1.0520x over previous
#include <cuda_runtime.h>
#include <cuda_bf16.h>
#include <cstdint>
#include <math.h>

#define SS 128
#define QQ 256
#define CC 256
#define HH 8
#define CHD 32
#define MROWS (SS*QQ)

// ---------------------------------------------------------------------------
// Helpers
// ---------------------------------------------------------------------------
__device__ __forceinline__ uint32_t smem_u32(const void* p) {
    uint32_t a;
    asm("{ .reg .u64 t; cvta.to.shared.u64 t, %1; cvt.u32.u64 %0, t; }" : "=r"(a) : "l"(p));
    return a;
}
__device__ __forceinline__ void cp16(uint32_t dst, const void* src) {
    asm volatile("cp.async.cg.shared.global [%0], [%1], 16;" :: "r"(dst), "l"(src));
}
__device__ __forceinline__ void ldmx4(uint32_t* f, uint32_t addr) {
    asm volatile("ldmatrix.sync.aligned.m8n8.x4.shared.b16 {%0,%1,%2,%3}, [%4];"
                 : "=r"(f[0]), "=r"(f[1]), "=r"(f[2]), "=r"(f[3]) : "r"(addr));
}
__device__ __forceinline__ void mma16816(float* c, const uint32_t* a, uint32_t b0, uint32_t b1) {
    asm volatile("mma.sync.aligned.m16n8k16.row.col.f32.bf16.bf16.f32 "
                 "{%0,%1,%2,%3}, {%4,%5,%6,%7}, {%8,%9}, {%0,%1,%2,%3};"
                 : "+f"(c[0]), "+f"(c[1]), "+f"(c[2]), "+f"(c[3])
                 : "r"(a[0]), "r"(a[1]), "r"(a[2]), "r"(a[3]), "r"(b0), "r"(b1));
}
__device__ __forceinline__ uint32_t packbf(float hi, float lo) {
    uint32_t pk;
    asm("cvt.rn.satfinite.bf16x2.f32 %0, %1, %2;" : "=r"(pk) : "f"(hi), "f"(lo));
    return pk;
}

// ---------------------------------------------------------------------------
// Scratch (device globals: allocation-free rule)
// ---------------------------------------------------------------------------
__device__ __nv_bfloat16 g_xb[MROWS * 256];        // input in bf16
__device__ __nv_bfloat16 g_wb[1024 * 256];         // packed wq|wk|wv|wg (wq pre-scaled)
__device__ __nv_bfloat16 g_wob[256 * 256];         // wo in bf16
__device__ __nv_bfloat16 g_qb[SS * HH * QQ * CHD]; // [s,h,q,d] bf16
__device__ __nv_bfloat16 g_kb[SS * HH * QQ * CHD];
__device__ __nv_bfloat16 g_vb[SS * HH * QQ * CHD];
__device__ __nv_bfloat16 g_gateb[MROWS * 256];     // sigmoid gate (bf16), [row, e]
__device__ __nv_bfloat16 g_ob[MROWS * 256];        // gated attention output (bf16)
__device__ __nv_bfloat16 g_biasb[HH * QQ * QQ];    // bias in bf16

// ---------------------------------------------------------------------------
// Prologue: one kernel, grid-partitioned (conv_x | conv_bias | pack_w)
// ---------------------------------------------------------------------------
__global__ void prep(const float* __restrict__ x, const float* __restrict__ bias,
                     const float* __restrict__ wq, const float* __restrict__ wk,
                     const float* __restrict__ wv, const float* __restrict__ wg,
                     const float* __restrict__ wo) {
    int b = blockIdx.x;
    if (b < 8192) {                       // conv_x
        int i = b * 256 + threadIdx.x;
        float4 v = ((const float4*)x)[i];
        __nv_bfloat162* dst = (__nv_bfloat162*)g_xb;
        dst[2 * i]     = __floats2bfloat162_rn(v.x, v.y);
        dst[2 * i + 1] = __floats2bfloat162_rn(v.z, v.w);
    } else if (b < 8704) {                // conv_bias
        int i = (b - 8192) * 256 + threadIdx.x;
        float4 v = ((const float4*)bias)[i];
        __nv_bfloat162* dst = (__nv_bfloat162*)g_biasb;
        dst[2 * i]     = __floats2bfloat162_rn(v.x, v.y);
        dst[2 * i + 1] = __floats2bfloat162_rn(v.z, v.w);
    } else {                              // pack_w
        int e = b - 8704;
        int c = threadIdx.x;
        if (e < 1024) {
            float val;
            if (e < 256)      val = wq[e * 256 + c] * 0.17677669529663687f;
            else if (e < 512) val = wk[(e - 256) * 256 + c];
            else if (e < 768) val = wv[(e - 512) * 256 + c];
            else              val = wg[(e - 768) * 256 + c];
            g_wb[e * 256 + c] = __float2bfloat16(val);
        } else {
            int r = e - 1024;
            g_wob[r * 256 + c] = __float2bfloat16(wo[r * 256 + c]);
        }
    }
}

// ---------------------------------------------------------------------------
// GEMM core: C[128,64] = A[128,256] x B[64,256]^T (NT, bf16, f32 acc)
// 8 warps as 4(M) x 2(N); per warp 32x32. 3-stage cp.async, 1 barrier/iter.
// ---------------------------------------------------------------------------
#define TILE_A 10240            // 128 rows * 80 bytes
#define TILE_BB 5120            // 64 rows * 80 bytes
#define STAGE_B (TILE_A + TILE_BB)
#define GEMM_SMEM (3 * STAGE_B) // 46080

__device__ __forceinline__ void gemm_core(const __nv_bfloat16* __restrict__ gA,
                                          const __nv_bfloat16* __restrict__ gB,
                                          char* smem,
                                          float acc[2][4][4]) {
    const int tid = threadIdx.x, lane = tid & 31, wid = tid >> 5;
    const int wm0 = (wid >> 1) * 32, wn0 = (wid & 1) * 32;
    const uint32_t sbase = smem_u32(smem);

    #pragma unroll
    for (int mt = 0; mt < 2; mt++)
        #pragma unroll
        for (int nt = 0; nt < 4; nt++)
            #pragma unroll
            for (int i = 0; i < 4; i++) acc[mt][nt][i] = 0.f;

    auto load_tile = [&](int buf, int k0) {
        uint32_t st = sbase + buf * STAGE_B;
        #pragma unroll
        for (int j = 0; j < 2; j++) {           // A: 512 chunks
            int idx = tid + j * 256;
            int r = idx >> 2, ch = idx & 3;
            cp16(st + r * 80 + ch * 16, gA + r * 256 + k0 + ch * 8);
        }
        {                                        // B: 256 chunks
            int r = tid >> 2, ch = tid & 3;
            cp16(st + TILE_A + r * 80 + ch * 16, gB + r * 256 + k0 + ch * 8);
        }
        asm volatile("cp.async.commit_group;" ::: "memory");
    };

    load_tile(0, 0);
    load_tile(1, 32);

    #pragma unroll
    for (int kit = 0; kit < 8; kit++) {
        if (kit < 7) {
            asm volatile("cp.async.wait_group 1;" ::: "memory");
        } else {
            asm volatile("cp.async.wait_group 0;" ::: "memory");
        }
        __syncthreads();   // all threads waited -> tile kit visible; compute kit-1 done
        if (kit < 6) {
            load_tile((kit + 2) % 3, (kit + 2) * 32);
        }
        const uint32_t ab = sbase + (kit % 3) * STAGE_B;
        const uint32_t bb = ab + TILE_A;
        #pragma unroll
        for (int kk = 0; kk < 2; kk++) {
            uint32_t af[2][4];
            #pragma unroll
            for (int mt = 0; mt < 2; mt++) {
                int row = wm0 + mt * 16 + (lane & 15);
                int col = kk * 16 + ((lane >> 4) << 3);
                ldmx4(af[mt], ab + row * 80 + col * 2);
            }
            #pragma unroll
            for (int nt2 = 0; nt2 < 2; nt2++) {
                uint32_t bf[4];
                int nrow = wn0 + nt2 * 16 + (lane & 7) + ((lane >> 4) << 3);
                int ncol = kk * 16 + (((lane >> 3) & 1) << 3);
                ldmx4(bf, bb + nrow * 80 + ncol * 2);
                #pragma unroll
                for (int mt = 0; mt < 2; mt++) {
                    mma16816(acc[mt][2 * nt2],     af[mt], bf[0], bf[1]);
                    mma16816(acc[mt][2 * nt2 + 1], af[mt], bf[2], bf[3]);
                }
            }
        }
    }
}

// ---------------------------------------------------------------------------
// GEMM1: Y[32768,1024] = Xb @ Wb^T. BN=64, grid (16, 256).
// ---------------------------------------------------------------------------
__global__ __launch_bounds__(256, 3) void gemm1_mma(const float* __restrict__ bg) {
    extern __shared__ char dynsm[];
    const int bn = blockIdx.x, bm = blockIdx.y;
    const int lane = threadIdx.x & 31, wid = threadIdx.x >> 5;
    const int wm0 = (wid >> 1) * 32, wn0 = (wid & 1) * 32;

    float acc[2][4][4];
    gemm_core(g_xb + (size_t)bm * 128 * 256, g_wb + (size_t)bn * 64 * 256, dynsm, acc);

    #pragma unroll
    for (int mt = 0; mt < 2; mt++) {
        #pragma unroll
        for (int nt = 0; nt < 4; nt++) {
            #pragma unroll
            for (int half = 0; half < 2; half++) {
                int m = bm * 128 + wm0 + mt * 16 + (lane >> 2) + half * 8;
                int e = bn * 64 + wn0 + nt * 8 + 2 * (lane & 3);
                float v0 = acc[mt][nt][2 * half];
                float v1 = acc[mt][nt][2 * half + 1];
                int s = m >> 8, q = m & 255;
                if (e < 768) {
                    int which = e >> 8;
                    int h = (e >> 5) & 7;
                    int d = e & 31;
                    __nv_bfloat16* dst = (which == 0 ? g_qb : (which == 1 ? g_kb : g_vb)) +
                                         ((size_t)(s * 8 + h) * 256 + q) * 32 + d;
                    *(uint32_t*)dst = packbf(v1, v0);
                } else {
                    int eg = e - 768;
                    float g0 = 1.0f / (1.0f + __expf(-(v0 + bg[eg])));
                    float g1 = 1.0f / (1.0f + __expf(-(v1 + bg[eg + 1])));
                    *(uint32_t*)(g_gateb + (size_t)m * 256 + eg) = packbf(g1, g0);
                }
            }
        }
    }
}

// ---------------------------------------------------------------------------
// GEMM2: out[q,s,c] = addt + g_ob @ wo^T + bo. BN=64, grid (4, 256).
// Coalesced epilogue: acc -> smem (128x66 f32) -> full-row 256B transactions.
// ---------------------------------------------------------------------------
#define EPI_PITCH 66   // floats per row (64 + 2 pad)

__global__ __launch_bounds__(256, 3) void gemm2_mma(const float* __restrict__ bo,
                                                    const float* __restrict__ addt,
                                                    float* __restrict__ out) {
    extern __shared__ char dynsm[];
    const int bn = blockIdx.x, bm = blockIdx.y;
    const int lane = threadIdx.x & 31, wid = threadIdx.x >> 5;
    const int wm0 = (wid >> 1) * 32, wn0 = (wid & 1) * 32;

    float acc[2][4][4];
    gemm_core(g_ob + (size_t)bm * 128 * 256, g_wob + (size_t)bn * 64 * 256, dynsm, acc);

    __syncthreads();   // mainloop fully done in all warps; smem reusable
    float* cs = (float*)dynsm;   // 128 x 66 floats = 33792 B

    #pragma unroll
    for (int mt = 0; mt < 2; mt++) {
        #pragma unroll
        for (int nt = 0; nt < 4; nt++) {
            #pragma unroll
            for (int half = 0; half < 2; half++) {
                int ml = wm0 + mt * 16 + (lane >> 2) + half * 8;
                int cl = wn0 + nt * 8 + 2 * (lane & 3);
                *(float2*)(cs + ml * EPI_PITCH + cl) =
                    make_float2(acc[mt][nt][2 * half], acc[mt][nt][2 * half + 1]);
            }
        }
    }
    __syncthreads();

    // per-lane column is fixed: c = lane*2
    float2 bo2 = *(const float2*)(bo + bn * 64 + lane * 2);
    #pragma unroll
    for (int r = 0; r < 16; r++) {
        int ml = wid * 16 + r;
        int m = bm * 128 + ml;
        int s = m >> 8, q = m & 255;
        size_t oi = ((size_t)q * 128 + s) * 256 + bn * 64 + lane * 2;
        float2 v = *(const float2*)(cs + ml * EPI_PITCH + lane * 2);
        float2 a2 = *(const float2*)(addt + oi);
        float2 r2;
        r2.x = a2.x + bo2.x + v.x;
        r2.y = a2.y + bo2.y + v.y;
        *(float2*)(out + oi) = r2;
    }
}

// ---------------------------------------------------------------------------
// Tensor-core flash attention (R11 form: direct bf16 bias loads).
// One CTA per (s,h), 8 warps x 32 q-rows.
// ---------------------------------------------------------------------------
#define QS_OFF   0         // 256 rows x 80B
#define KS_OFF   20480     // 256 rows x 80B
#define VT_OFF   40960     // Vt: 32 rows x 528B
#define MADD_OFF 57856     // 256 floats
#define ATTN_SMEM 58880

__global__ __launch_bounds__(256) void attn_tc(const float* __restrict__ mask) {
    extern __shared__ char smp[];
    const uint32_t sb = smem_u32(smp);
    const int s = blockIdx.x >> 3;
    const int h = blockIdx.x & 7;
    const int t = threadIdx.x;
    const int lane = t & 31, w = t >> 5;

    const size_t hb = (size_t)(s * 8 + h) * 16384;   // byte offset of this (s,h) tile

    // cp.async Q, K tiles into 80B-pitch smem
    #pragma unroll
    for (int j = 0; j < 4; j++) {
        int idx = t + j * 256;
        int r = idx >> 2, ch = idx & 3;
        cp16(sb + QS_OFF + r * 80 + ch * 16, (const char*)g_qb + hb + r * 64 + ch * 16);
        cp16(sb + KS_OFF + r * 80 + ch * 16, (const char*)g_kb + hb + r * 64 + ch * 16);
    }
    asm volatile("cp.async.commit_group;" ::: "memory");

    // V transpose: thread t reads V row k=t (32 bf16), scatters to Vt[d][k=t]
    {
        union { uint4 v4[4]; uint16_t u16[32]; } tv;
        const uint4* vr = (const uint4*)((const char*)g_vb + hb + t * 64);
        tv.v4[0] = vr[0]; tv.v4[1] = vr[1]; tv.v4[2] = vr[2]; tv.v4[3] = vr[3];
        #pragma unroll
        for (int d = 0; d < 32; d++)
            *(uint16_t*)(smp + VT_OFF + d * 528 + 2 * t) = tv.u16[d];
    }
    // mask additive term
    *(float*)(smp + MADD_OFF + 4 * t) = (mask[s * 256 + t] - 1.0f) * 1e9f;

    asm volatile("cp.async.wait_group 0;" ::: "memory");
    __syncthreads();

    // Q fragments for this warp's 32 rows
    uint32_t af[2][2][4];   // [mt][kstep]
    #pragma unroll
    for (int mt = 0; mt < 2; mt++)
        #pragma unroll
        for (int ks = 0; ks < 2; ks++) {
            int row = 32 * w + mt * 16 + (lane & 15);
            int col = ks * 16 + ((lane >> 4) << 3);
            ldmx4(af[mt][ks], sb + QS_OFF + row * 80 + col * 2);
        }

    float o_acc[2][4][4];
    #pragma unroll
    for (int mt = 0; mt < 2; mt++)
        #pragma unroll
        for (int nt = 0; nt < 4; nt++)
            #pragma unroll
            for (int i = 0; i < 4; i++) o_acc[mt][nt][i] = 0.f;
    float lsum[2][2] = {};

    const int r_lo = (lane >> 2);         // row-in-tile for c0,c1
    const int jo   = 2 * (lane & 3);      // col pair offset

    for (int c = 0; c < 8; c++) {
        // ---- S = Q K^T for this 32-key chunk ----
        float s_acc[2][4][4];
        #pragma unroll
        for (int mt = 0; mt < 2; mt++)
            #pragma unroll
            for (int nt = 0; nt < 4; nt++)
                #pragma unroll
                for (int i = 0; i < 4; i++) s_acc[mt][nt][i] = 0.f;

        #pragma unroll
        for (int ks = 0; ks < 2; ks++) {
            #pragma unroll
            for (int nt2 = 0; nt2 < 2; nt2++) {
                uint32_t bf[4];
                int nrow = c * 32 + nt2 * 16 + (lane & 7) + ((lane >> 4) << 3);
                int ncol = ks * 16 + (((lane >> 3) & 1) << 3);
                ldmx4(bf, sb + KS_OFF + nrow * 80 + ncol * 2);
                #pragma unroll
                for (int mt = 0; mt < 2; mt++) {
                    mma16816(s_acc[mt][2 * nt2],     af[mt][ks], bf[0], bf[1]);
                    mma16816(s_acc[mt][2 * nt2 + 1], af[mt][ks], bf[2], bf[3]);
                }
            }
        }

        // ---- bias(bf16) + mask, exp, pack P fragments ----
        uint32_t pfrag[2][4][2];
        #pragma unroll
        for (int mt = 0; mt < 2; mt++) {
            int r0 = 32 * w + mt * 16 + r_lo;
            #pragma unroll
            for (int nt = 0; nt < 4; nt++) {
                int j = c * 32 + nt * 8 + jo;
                float2 mj = *(const float2*)(smp + MADD_OFF + 4 * j);
                __nv_bfloat162 bb0 = *(const __nv_bfloat162*)(g_biasb + ((size_t)(h * 256 + r0) * 256 + j));
                __nv_bfloat162 bb1 = *(const __nv_bfloat162*)(g_biasb + ((size_t)(h * 256 + r0 + 8) * 256 + j));
                float2 b0 = __bfloat1622float2(bb0);
                float2 b1 = __bfloat1622float2(bb1);
                float w00 = __expf(fminf(s_acc[mt][nt][0] + b0.x + mj.x, 80.f));
                float w01 = __expf(fminf(s_acc[mt][nt][1] + b0.y + mj.y, 80.f));
                float w10 = __expf(fminf(s_acc[mt][nt][2] + b1.x + mj.x, 80.f));
                float w11 = __expf(fminf(s_acc[mt][nt][3] + b1.y + mj.y, 80.f));
                lsum[mt][0] += w00 + w01;
                lsum[mt][1] += w10 + w11;
                pfrag[mt][nt][0] = packbf(w01, w00);
                pfrag[mt][nt][1] = packbf(w11, w10);
            }
        }

        // ---- O += P V ----
        #pragma unroll
        for (int ks2 = 0; ks2 < 2; ks2++) {
            uint32_t bv[2][4];
            #pragma unroll
            for (int nv = 0; nv < 2; nv++) {
                int nrow = nv * 16 + (lane & 7) + ((lane >> 4) << 3);
                int ncol = c * 32 + ks2 * 16 + (((lane >> 3) & 1) << 3);
                ldmx4(bv[nv], sb + VT_OFF + nrow * 528 + ncol * 2);
            }
            #pragma unroll
            for (int mt = 0; mt < 2; mt++) {
                uint32_t aP[4] = { pfrag[mt][2 * ks2][0], pfrag[mt][2 * ks2][1],
                                   pfrag[mt][2 * ks2 + 1][0], pfrag[mt][2 * ks2 + 1][1] };
                #pragma unroll
                for (int nv = 0; nv < 2; nv++) {
                    mma16816(o_acc[mt][2 * nv],     aP, bv[nv][0], bv[nv][1]);
                    mma16816(o_acc[mt][2 * nv + 1], aP, bv[nv][2], bv[nv][3]);
                }
            }
        }
    }

    // ---- row-sum reduce + normalize + gate + store ----
    float inv[2][2];
    #pragma unroll
    for (int mt = 0; mt < 2; mt++)
        #pragma unroll
        for (int half = 0; half < 2; half++) {
            float lv = lsum[mt][half];
            lv += __shfl_xor_sync(0xffffffffu, lv, 1);
            lv += __shfl_xor_sync(0xffffffffu, lv, 2);
            inv[mt][half] = 1.0f / lv;
        }

    #pragma unroll
    for (int mt = 0; mt < 2; mt++) {
        int q0 = 32 * w + mt * 16 + r_lo;
        int row0 = s * 256 + q0;
        #pragma unroll
        for (int nv = 0; nv < 4; nv++) {
            int d = nv * 8 + jo;
            __nv_bfloat162 gav = *(const __nv_bfloat162*)(g_gateb + (size_t)row0 * 256 + h * 32 + d);
            __nv_bfloat162 gbv = *(const __nv_bfloat162*)(g_gateb + (size_t)(row0 + 8) * 256 + h * 32 + d);
            float2 ga = __bfloat1622float2(gav);
            float2 gb = __bfloat1622float2(gbv);
            float v00 = o_acc[mt][nv][0] * inv[mt][0] * ga.x;
            float v01 = o_acc[mt][nv][1] * inv[mt][0] * ga.y;
            float v10 = o_acc[mt][nv][2] * inv[mt][1] * gb.x;
            float v11 = o_acc[mt][nv][3] * inv[mt][1] * gb.y;
            *(uint32_t*)(g_ob + (size_t)row0 * 256 + h * 32 + d) = packbf(v01, v00);
            *(uint32_t*)(g_ob + (size_t)(row0 + 8) * 256 + h * 32 + d) = packbf(v11, v10);
        }
    }
}

// ---------------------------------------------------------------------------
extern "C" void kernel_launch(void* const* d_in, const int* in_sizes, int n_in,
                              void* d_out, int out_size) {
    const float* x    = (const float*)d_in[0];
    const float* mask = (const float*)d_in[1];
    const float* bias = (const float*)d_in[2];
    const float* addt = (const float*)d_in[3];
    const float* wq   = (const float*)d_in[4];
    const float* wk   = (const float*)d_in[5];
    const float* wv   = (const float*)d_in[6];
    const float* wg   = (const float*)d_in[7];
    const float* bg   = (const float*)d_in[8];
    const float* wo   = (const float*)d_in[9];
    const float* bo   = (const float*)d_in[10];
    float* out = (float*)d_out;

    cudaFuncSetAttribute(attn_tc, cudaFuncAttributeMaxDynamicSharedMemorySize, ATTN_SMEM);
    cudaFuncSetAttribute(gemm1_mma, cudaFuncAttributeMaxDynamicSharedMemorySize, GEMM_SMEM);
    cudaFuncSetAttribute(gemm2_mma, cudaFuncAttributeMaxDynamicSharedMemorySize, GEMM_SMEM);

    prep<<<9984, 256>>>(x, bias, wq, wk, wv, wg, wo);

    gemm1_mma<<<dim3(16, 256), 256, GEMM_SMEM>>>(bg);
    attn_tc<<<1024, 256, ATTN_SMEM>>>(mask);
    gemm2_mma<<<dim3(4, 256), 256, GEMM_SMEM>>>(bo, addt, out);
}